// round 15
// baseline (speedup 1.0000x reference)
#include <cuda_runtime.h>
#include <cuda_fp16.h>
#include <cuda_bf16.h>
#include <math.h>
#include <stdint.h>

// ---------------- problem constants ----------------
#define BQ 2
#define LQ 2048
#define MROWS (BQ * LQ)     // 4096
#define DQ 256
#define SQ 8
#define DEPTHQ 4
#define DSQ (DQ + SQ)       // 264
#define NEXT 272            // 264 + 8 gate cols
#define KPAD 288            // padded K for layer GEMMs
#define VOCABQ 32000

typedef __nv_bfloat16 bf16;
typedef __nv_bfloat162 bf162;

// ---------------- scratch (no allocations; zero-init pads load-bearing) ----
__device__ __align__(256) bf16 g_Xh[MROWS * KPAD];
__device__ __align__(256) bf16 g_Xl[MROWS * KPAD];
__device__ __align__(256) bf16 g_Yh[MROWS * KPAD];
__device__ __align__(256) bf16 g_Yl[MROWS * KPAD];
__device__ __align__(256) bf16 g_Ch[MROWS * KPAD];
__device__ __align__(256) bf16 g_Cl[MROWS * KPAD];
__device__ float g_state[MROWS * SQ];
__device__ float g_gatebuf[MROWS * SQ];
__device__ __align__(256) bf16 g_Wieh[DEPTHQ * NEXT * KPAD];
__device__ __align__(256) bf16 g_Wiel[DEPTHQ * NEXT * KPAD];
__device__ __align__(256) bf16 g_Woth[DEPTHQ * DQ * KPAD];
__device__ __align__(256) bf16 g_Wotl[DEPTHQ * DQ * KPAD];
__device__ float g_bie[DEPTHQ * NEXT];
__device__ __align__(256) __half g_Af[MROWS * DQ];
__device__ __align__(256) __half g_Bt[(size_t)VOCABQ * DQ];
__device__ __align__(256) __half g_Wrt[DQ * DQ];

// ================= PTX helpers (base sm_103 ISA only) =================
__device__ __forceinline__ uint32_t smem_u32(const void* p) {
    uint32_t a;
    asm("{ .reg .u64 t; cvta.to.shared.u64 t, %1; cvt.u32.u64 %0, t; }" : "=r"(a) : "l"(p));
    return a;
}
__device__ __forceinline__ void cpa16(uint32_t dst, const void* src) {
    asm volatile("cp.async.cg.shared.global [%0], [%1], 16;" :: "r"(dst), "l"(src));
}
__device__ __forceinline__ void cpa_commit() { asm volatile("cp.async.commit_group;" ::: "memory"); }
__device__ __forceinline__ void cpa_wait2()  { asm volatile("cp.async.wait_group 2;" ::: "memory"); }
__device__ __forceinline__ void cpa_wait1()  { asm volatile("cp.async.wait_group 1;" ::: "memory"); }
__device__ __forceinline__ void cpa_wait0()  { asm volatile("cp.async.wait_group 0;" ::: "memory"); }

__device__ __forceinline__ void ldmx4(uint32_t* r, uint32_t addr) {
    asm volatile("ldmatrix.sync.aligned.m8n8.x4.shared.b16 {%0,%1,%2,%3}, [%4];"
                 : "=r"(r[0]), "=r"(r[1]), "=r"(r[2]), "=r"(r[3]) : "r"(addr));
}
__device__ __forceinline__ void mma16816(float* d, const uint32_t* a, uint32_t b0, uint32_t b1) {
    asm volatile(
        "mma.sync.aligned.m16n8k16.row.col.f32.f16.f16.f32 "
        "{%0,%1,%2,%3}, {%4,%5,%6,%7}, {%8,%9}, {%0,%1,%2,%3};"
        : "+f"(d[0]), "+f"(d[1]), "+f"(d[2]), "+f"(d[3])
        : "r"(a[0]), "r"(a[1]), "r"(a[2]), "r"(a[3]), "r"(b0), "r"(b1));
}
__device__ __forceinline__ void mma16816bf(float* d, const uint32_t* a, uint32_t b0, uint32_t b1) {
    asm volatile(
        "mma.sync.aligned.m16n8k16.row.col.f32.bf16.bf16.f32 "
        "{%0,%1,%2,%3}, {%4,%5,%6,%7}, {%8,%9}, {%0,%1,%2,%3};"
        : "+f"(d[0]), "+f"(d[1]), "+f"(d[2]), "+f"(d[3])
        : "r"(a[0]), "r"(a[1]), "r"(a[2]), "r"(a[3]), "r"(b0), "r"(b1));
}
__device__ __forceinline__ void splitbf(float v, bf16& h, bf16& l) {
    h = __float2bfloat16_rn(v);
    l = __float2bfloat16_rn(v - __bfloat162float(h));
}

// ================= fp16 GEMM (r12 proven): CTA 128x128, 8 warps (2x4), ====
// warp 64x32, depth-3 cp.async pipeline (4 buffers), logits+recon merged.
// Column tiles 0..249 -> logits (Bt, bc); tile 250..251 -> recon (Wrt, br).
#define TCM 128
#define TCN 128
#define F16_STG (TCM * 40 + TCN * 40)      // halfs per stage (10240 = 20480 B)
#define F16_NST 4
#define F16_SMEM (F16_NST * F16_STG * 2)   // 81920 B

__global__ __launch_bounds__(256, 2)
void hgemm_f16(const __half* __restrict__ A, const __half* __restrict__ Bt,
               const __half* __restrict__ Wrt,
               const float* __restrict__ bc, const float* __restrict__ br,
               float* __restrict__ logits, float* __restrict__ recon) {
    extern __shared__ __half hsm[];
    const uint32_t sb0 = smem_u32(hsm);
    const int tid = threadIdx.x;
    const int wid = tid >> 5, lane = tid & 31;
    const int wm = wid & 1, wn = wid >> 1;
    const int m0 = blockIdx.y * TCM;
    const int n0 = blockIdx.x * TCN;

    const bool is_recon = (n0 >= VOCABQ);
    const int cb = is_recon ? (n0 - VOCABQ) : n0;
    const __half* Bbase = is_recon ? (Wrt + (size_t)cb * DQ) : (Bt + (size_t)n0 * DQ);
    const float* bias = (is_recon ? br : bc) + cb;
    float* C = is_recon ? recon : logits;
    const int ldc = is_recon ? DQ : VOCABQ;

    float acc[4][4][4];
#pragma unroll
    for (int i = 0; i < 4; i++)
#pragma unroll
        for (int j = 0; j < 4; j++)
#pragma unroll
            for (int q = 0; q < 4; q++) acc[i][j][q] = 0.f;

    auto load_stage = [&](int s, int k0) {
        const uint32_t ab = sb0 + s * F16_STG * 2;
        const uint32_t bb = ab + TCM * 40 * 2;
#pragma unroll
        for (int it = 0; it < 2; it++) {
            int i = tid + it * 256;
            int r = i >> 2, c = i & 3;
            cpa16(ab + r * 80 + c * 16, A + (size_t)(m0 + r) * DQ + k0 + c * 8);
        }
#pragma unroll
        for (int it = 0; it < 2; it++) {
            int i = tid + it * 256;
            int r = i >> 2, c = i & 3;
            cpa16(bb + r * 80 + c * 16, Bbase + (size_t)r * DQ + k0 + c * 8);
        }
        cpa_commit();
    };

    load_stage(0, 0);
    load_stage(1, 32);
    load_stage(2, 64);
    const int lrow = lane & 15;
    const int lhalf = lane >> 4;

    for (int kt = 0; kt < 8; kt++) {
        if (kt <= 5)      cpa_wait2();
        else if (kt == 6) cpa_wait1();
        else              cpa_wait0();
        __syncthreads();
        if (kt < 5) load_stage((kt + 3) % F16_NST, (kt + 3) * 32);

        const uint32_t ab = sb0 + (kt % F16_NST) * F16_STG * 2;
        const uint32_t bb = ab + TCM * 40 * 2;
#pragma unroll
        for (int ks = 0; ks < 2; ks++) {
            const int chunk = ks * 2 + lhalf;
            uint32_t af[4][4], bf[2][4];
#pragma unroll
            for (int mi = 0; mi < 4; mi++)
                ldmx4(af[mi], ab + (wm * 64 + mi * 16 + lrow) * 80 + chunk * 16);
#pragma unroll
            for (int bj = 0; bj < 2; bj++)
                ldmx4(bf[bj], bb + (wn * 32 + bj * 16 + lrow) * 80 + chunk * 16);
#pragma unroll
            for (int mi = 0; mi < 4; mi++)
#pragma unroll
                for (int nj = 0; nj < 4; nj++) {
                    int bj = nj >> 1, hi = nj & 1;
                    mma16816(acc[mi][nj], af[mi], bf[bj][hi], bf[bj][hi + 2]);
                }
        }
    }

    const int g = lane >> 2, tig = lane & 3;
#pragma unroll
    for (int mi = 0; mi < 4; mi++) {
#pragma unroll
        for (int nj = 0; nj < 4; nj++) {
            int col = wn * 32 + nj * 8 + 2 * tig;         // local within tile
            float bx = __ldg(bias + col), by = __ldg(bias + col + 1);
            int row0 = m0 + wm * 64 + mi * 16 + g;
            size_t o0 = (size_t)row0 * ldc + cb + col;
            *(float2*)(C + o0) =
                make_float2(acc[mi][nj][0] + bx, acc[mi][nj][1] + by);
            *(float2*)(C + o0 + (size_t)8 * ldc) =
                make_float2(acc[mi][nj][2] + bx, acc[mi][nj][3] + by);
        }
    }
}

// ================= bf16-split GEMM, single-sync depth-2+ (3 buffers) ======
// C = (Ah+Al)[M][K] * (Bh+Bl)[N][K]^T + bias  (3-term compensated)
// CTA 64x128, 4 warps, warp 64x32, K = nkt*32 (runtime chunk count <= 9).
#define LTM 64
#define LTN 128
#define SAH 0
#define SAL (64 * 40)
#define SBH (2 * 64 * 40)
#define SBL (2 * 64 * 40 + 128 * 40)
#define STG (2 * 64 * 40 + 2 * 128 * 40)   // bf16 elems per stage (15360)
#define SPLIT_NST 3
#define SPLIT_SMEM (SPLIT_NST * STG * 2)   // bytes = 92160

__global__ __launch_bounds__(128)
void hgemm_split(const bf16* __restrict__ Ah, const bf16* __restrict__ Al,
                 const bf16* __restrict__ Bh, const bf16* __restrict__ Bl,
                 int nrowsB, const float* __restrict__ bias, int nbias, int mode,
                 int nkt,
                 bf16* __restrict__ outh, bf16* __restrict__ outl,
                 float* __restrict__ statep, float* __restrict__ gatep) {
    extern __shared__ bf16 sm[];
    const int tid = threadIdx.x;
    const int wn = tid >> 5, lane = tid & 31;
    const int m0 = blockIdx.y * LTM;
    const int n0 = blockIdx.x * LTN;

    float acc[4][4][4];
#pragma unroll
    for (int i = 0; i < 4; i++)
#pragma unroll
        for (int j = 0; j < 4; j++)
#pragma unroll
            for (int q = 0; q < 4; q++) acc[i][j][q] = 0.f;

    const uint32_t sb0 = smem_u32(sm);

    auto load_stage = [&](int s, int k0) {
        const uint32_t sb = sb0 + s * STG * 2;
#pragma unroll
        for (int it = 0; it < 2; it++) {
            int i = tid + it * 128;                 // A rows 64 x 4 chunks
            int r = i >> 2, c = i & 3;
            size_t goff = (size_t)(m0 + r) * KPAD + k0 + c * 8;
            cpa16(sb + (SAH + r * 40) * 2 + c * 16, Ah + goff);
            cpa16(sb + (SAL + r * 40) * 2 + c * 16, Al + goff);
        }
#pragma unroll
        for (int it = 0; it < 4; it++) {
            int i = tid + it * 128;                 // B rows 128 x 4 chunks
            int r = i >> 2, c = i & 3;
            int rr = n0 + r; if (rr >= nrowsB) rr = 0;
            size_t goff = (size_t)rr * KPAD + k0 + c * 8;
            cpa16(sb + (SBH + r * 40) * 2 + c * 16, Bh + goff);
            cpa16(sb + (SBL + r * 40) * 2 + c * 16, Bl + goff);
        }
        cpa_commit();
    };

    load_stage(0, 0);
    load_stage(1, 32);
    const int lrow = lane & 15;
    const int lhalf = lane >> 4;

    for (int kt = 0; kt < nkt; kt++) {
        if (kt < nkt - 1) cpa_wait1(); else cpa_wait0();
        __syncthreads();                             // fences compute kt-1
        if (kt + 2 < nkt) load_stage((kt + 2) % SPLIT_NST, (kt + 2) * 32);

        const uint32_t sb = sb0 + (kt % SPLIT_NST) * STG * 2;
#pragma unroll
        for (int ks = 0; ks < 2; ks++) {
            const int chunk = ks * 2 + lhalf;
            uint32_t afh[4][4], afl[4][4], bfh[2][4], bfl[2][4];
#pragma unroll
            for (int mi = 0; mi < 4; mi++) {
                int r = mi * 16 + lrow;
                ldmx4(afh[mi], sb + (SAH + r * 40) * 2 + chunk * 16);
                ldmx4(afl[mi], sb + (SAL + r * 40) * 2 + chunk * 16);
            }
#pragma unroll
            for (int bj = 0; bj < 2; bj++) {
                int r = wn * 32 + bj * 16 + lrow;
                ldmx4(bfh[bj], sb + (SBH + r * 40) * 2 + chunk * 16);
                ldmx4(bfl[bj], sb + (SBL + r * 40) * 2 + chunk * 16);
            }
#pragma unroll
            for (int mi = 0; mi < 4; mi++)
#pragma unroll
                for (int nj = 0; nj < 4; nj++) {
                    int bj = nj >> 1, hi = nj & 1;
                    mma16816bf(acc[mi][nj], afh[mi], bfh[bj][hi], bfh[bj][hi + 2]);
                    mma16816bf(acc[mi][nj], afl[mi], bfh[bj][hi], bfh[bj][hi + 2]);
                    mma16816bf(acc[mi][nj], afh[mi], bfl[bj][hi], bfl[bj][hi + 2]);
                }
        }
    }

    const int g = lane >> 2, tig = lane & 3;
#pragma unroll
    for (int mi = 0; mi < 4; mi++) {
#pragma unroll
        for (int nj = 0; nj < 4; nj++) {
            int col = n0 + wn * 32 + nj * 8 + 2 * tig;
            if (col >= nbias) continue;
            float bx = __ldg(bias + col), by = __ldg(bias + col + 1);
            int r0 = m0 + mi * 16 + g;
#pragma unroll
            for (int half = 0; half < 2; half++) {
                int r = r0 + half * 8;
                float v0 = acc[mi][nj][half * 2 + 0] + bx;
                float v1 = acc[mi][nj][half * 2 + 1] + by;
                if (mode == 0 || col < 256) {
                    bf16 h0, l0, h1, l1;
                    splitbf(v0, h0, l0); splitbf(v1, h1, l1);
                    *(bf162*)(outh + (size_t)r * KPAD + col) = __halves2bfloat162(h0, h1);
                    *(bf162*)(outl + (size_t)r * KPAD + col) = __halves2bfloat162(l0, l1);
                } else if (col < 264) {
                    *(float2*)(statep + r * SQ + (col - 256)) = make_float2(v0, v1);
                } else {  // 264..271
                    gatep[r * SQ + (col - 264)]     = 1.f / (1.f + expf(-v0));
                    gatep[r * SQ + (col - 264) + 1] = 1.f / (1.f + expf(-v1));
                }
            }
        }
    }
}

// ================= weight prep kernels =================
__global__ void prep_wie(const float* __restrict__ Wi, const float* __restrict__ Wg,
                         const float* __restrict__ bi, const float* __restrict__ bg,
                         bf16* __restrict__ Wh, bf16* __restrict__ Wl,
                         float* __restrict__ bie) {
    int n = blockIdx.x, l = blockIdx.y, k = threadIdx.x;   // k in 0..255
    const float* Wil = Wi + (size_t)l * DQ * DSQ;
    const float* Wgl = Wg + (size_t)l * DSQ * SQ;
    float w;
    if (n < DSQ) {
        w = Wil[k * DSQ + n];
    } else {
        int s = n - DSQ;
        float a = 0.f;
        for (int e = 0; e < DSQ; e++) a += Wil[k * DSQ + e] * Wgl[e * SQ + s];
        w = a;
    }
    bf16 h, lo; splitbf(w, h, lo);
    size_t o = ((size_t)l * NEXT + n) * KPAD + k;
    Wh[o] = h; Wl[o] = lo;
    if (k == 0) {
        float b;
        if (n < DSQ) b = bi[l * DSQ + n];
        else {
            int s = n - DSQ;
            float a = bg[l * SQ + s];
            for (int e = 0; e < DSQ; e++) a += bi[l * DSQ + e] * Wgl[e * SQ + s];
            b = a;
        }
        bie[l * NEXT + n] = b;
    }
}

__global__ void prep_wot(const float* __restrict__ Wo,
                         bf16* __restrict__ Wh, bf16* __restrict__ Wl) {
    int e = blockIdx.x, l = blockIdx.y, d = threadIdx.x;
    float w = Wo[((size_t)l * DSQ + e) * DQ + d];
    bf16 h, lo; splitbf(w, h, lo);
    size_t o = ((size_t)l * DQ + d) * KPAD + e;
    Wh[o] = h; Wl[o] = lo;
}

// generic [256][ncols] f32 -> [ncols][256] fp16 transpose
__global__ __launch_bounds__(256)
void transpose_f32_to_f16(const float* __restrict__ src, __half* __restrict__ dst, int ncols) {
    __shared__ float t[32][33];
    const int n0 = blockIdx.x * 32;
    const int k0 = blockIdx.y * 32;
    const int tx = threadIdx.x, ty = threadIdx.y;   // 32 x 8
#pragma unroll
    for (int r = 0; r < 4; r++)
        t[ty * 4 + r][tx] = src[(size_t)(k0 + ty * 4 + r) * ncols + n0 + tx];
    __syncthreads();
#pragma unroll
    for (int r = 0; r < 4; r++)
        dst[(size_t)(n0 + ty * 4 + r) * DQ + k0 + tx] = __float2half_rn(t[tx][ty * 4 + r]);
}

// ---------------- embed gather -> split bf16 ----------------
__global__ void embed_kernel(const int* __restrict__ x_t,
                             const float* __restrict__ table,
                             bf16* __restrict__ hh, bf16* __restrict__ hl) {
    int i = blockIdx.x * blockDim.x + threadIdx.x;   // over MROWS*128
    if (i >= MROWS * 128) return;
    int row = i >> 7;
    int d0 = (i & 127) * 2;
    const float* tr = table + (size_t)x_t[row] * DQ + d0;
    float v0 = tr[0], v1 = tr[1];
    bf16 h0, l0, h1, l1;
    splitbf(v0, h0, l0); splitbf(v1, h1, l1);
    *(bf162*)(hh + (size_t)row * KPAD + d0) = __halves2bfloat162(h0, h1);
    *(bf162*)(hl + (size_t)row * KPAD + d0) = __halves2bfloat162(l0, l1);
}

// ---------------- parallel scan over L ----------------
#define SCAN_T 256
#define SCAN_STEPS (LQ / SCAN_T)   // 8

__global__ __launch_bounds__(SCAN_T)
void scan_kernel(const float* __restrict__ gate,
                 const float* __restrict__ state_in,
                 bf16* __restrict__ combh, bf16* __restrict__ combl,
                 float* __restrict__ out_states) {
    const int b = blockIdx.x >> 3;
    const int s = blockIdx.x & 7;
    const int t = threadIdx.x;
    const int l0 = t * SCAN_STEPS;

    float g[SCAN_STEPS], si[SCAN_STEPS];
#pragma unroll
    for (int u = 0; u < SCAN_STEPS; u++) {
        int idx = b * LQ + l0 + u;
        g[u]  = gate[idx * SQ + s];
        si[u] = state_in[idx * SQ + s];
    }

    float a = 1.f, bb = 0.f;
#pragma unroll
    for (int u = 0; u < SCAN_STEPS; u++) {
        a  = g[u] * a;
        bb = g[u] * bb + (1.f - g[u]) * si[u];
    }

    __shared__ float sa[SCAN_T], sbv[SCAN_T];
    sa[t] = a; sbv[t] = bb;
    __syncthreads();

#pragma unroll
    for (int off = 1; off < SCAN_T; off <<= 1) {
        float pa = 1.f, pb = 0.f, ca = sa[t], cb = sbv[t];
        if (t >= off) { pa = sa[t - off]; pb = sbv[t - off]; }
        __syncthreads();
        if (t >= off) { sa[t] = ca * pa; sbv[t] = ca * pb + cb; }
        __syncthreads();
    }

    float st = (t == 0) ? 0.f : sbv[t - 1];
#pragma unroll
    for (int u = 0; u < SCAN_STEPS; u++) {
        int idx = b * LQ + l0 + u;
        st = g[u] * st + (1.f - g[u]) * si[u];
        bf16 h, lo; splitbf(st, h, lo);
        combh[(size_t)idx * KPAD + DQ + s] = h;
        combl[(size_t)idx * KPAD + DQ + s] = lo;
    }
    if (t == SCAN_T - 1) out_states[b * SQ + s] = st;
}

// ---------------- layernorm: (hi+lo) fp32 math -> fp16 out ----------------
__global__ __launch_bounds__(256)
void layernorm_kernel(const bf16* __restrict__ xh, const bf16* __restrict__ xl,
                      const float* __restrict__ gamma, const float* __restrict__ beta,
                      __half* __restrict__ y) {
    int warp = (blockIdx.x * blockDim.x + threadIdx.x) >> 5;
    int lane = threadIdx.x & 31;
    if (warp >= MROWS) return;
    const bf16* xhr = xh + (size_t)warp * KPAD;
    const bf16* xlr = xl + (size_t)warp * KPAD;
    float v[8];
    float sum = 0.f;
#pragma unroll
    for (int i = 0; i < 8; i++) {
        int d = lane + i * 32;
        v[i] = __bfloat162float(xhr[d]) + __bfloat162float(xlr[d]);
        sum += v[i];
    }
#pragma unroll
    for (int o = 16; o; o >>= 1) sum += __shfl_xor_sync(0xFFFFFFFFu, sum, o);
    float mu = sum * (1.f / 256.f);
    float vs = 0.f;
#pragma unroll
    for (int i = 0; i < 8; i++) { float d = v[i] - mu; vs += d * d; }
#pragma unroll
    for (int o = 16; o; o >>= 1) vs += __shfl_xor_sync(0xFFFFFFFFu, vs, o);
    float r = rsqrtf(vs * (1.f / 256.f) + 1e-5f);
    __half* yr = y + (size_t)warp * DQ;
#pragma unroll
    for (int i = 0; i < 8; i++) {
        int d = lane + i * 32;
        yr[d] = __float2half_rn((v[i] - mu) * r * gamma[d] + beta[d]);
    }
}

// ---------------- launch ----------------
extern "C" void kernel_launch(void* const* d_in, const int* in_sizes, int n_in,
                              void* d_out, int out_size) {
    const int*   x_t   = (const int*)  d_in[0];
    const float* table = (const float*)d_in[1];
    const float* Wi    = (const float*)d_in[2];
    const float* bi    = (const float*)d_in[3];
    const float* Wg    = (const float*)d_in[4];
    const float* bg    = (const float*)d_in[5];
    const float* Wo    = (const float*)d_in[6];
    const float* bo    = (const float*)d_in[7];
    const float* gamma = (const float*)d_in[8];
    const float* beta  = (const float*)d_in[9];
    const float* Wc    = (const float*)d_in[10];
    const float* bc    = (const float*)d_in[11];
    const float* Wr    = (const float*)d_in[12];
    const float* br    = (const float*)d_in[13];

    float* out = (float*)d_out;
    const size_t logits_elems = (size_t)MROWS * VOCABQ;
    const size_t recon_elems  = (size_t)MROWS * DQ;
    float* logits  = out;
    float* recon   = out + logits_elems;
    float* ostates = out + logits_elems + recon_elems;

    bf16 *Xh, *Xl, *Yh, *Yl, *Ch, *Cl, *Wieh, *Wiel, *Woth, *Wotl;
    __half *Af, *Bt, *Wrt;
    float *statep, *gatep, *bie;
    cudaGetSymbolAddress((void**)&Xh, g_Xh);     cudaGetSymbolAddress((void**)&Xl, g_Xl);
    cudaGetSymbolAddress((void**)&Yh, g_Yh);     cudaGetSymbolAddress((void**)&Yl, g_Yl);
    cudaGetSymbolAddress((void**)&Ch, g_Ch);     cudaGetSymbolAddress((void**)&Cl, g_Cl);
    cudaGetSymbolAddress((void**)&Wieh, g_Wieh); cudaGetSymbolAddress((void**)&Wiel, g_Wiel);
    cudaGetSymbolAddress((void**)&Woth, g_Woth); cudaGetSymbolAddress((void**)&Wotl, g_Wotl);
    cudaGetSymbolAddress((void**)&Af, g_Af);     cudaGetSymbolAddress((void**)&Bt, g_Bt);
    cudaGetSymbolAddress((void**)&Wrt, g_Wrt);
    cudaGetSymbolAddress((void**)&statep, g_state);
    cudaGetSymbolAddress((void**)&gatep, g_gatebuf);
    cudaGetSymbolAddress((void**)&bie, g_bie);

    cudaFuncSetAttribute(hgemm_split, cudaFuncAttributeMaxDynamicSharedMemorySize, SPLIT_SMEM);
    cudaFuncSetAttribute(hgemm_f16,   cudaFuncAttributeMaxDynamicSharedMemorySize, F16_SMEM);

    // ---- weight prep ----
    prep_wie<<<dim3(NEXT, DEPTHQ), 256>>>(Wi, Wg, bi, bg, Wieh, Wiel, bie);
    prep_wot<<<dim3(DSQ, DEPTHQ), 256>>>(Wo, Woth, Wotl);
    transpose_f32_to_f16<<<dim3(VOCABQ / 32, DQ / 32), dim3(32, 8)>>>(Wc, Bt, VOCABQ);
    transpose_f32_to_f16<<<dim3(DQ / 32, DQ / 32), dim3(32, 8)>>>(Wr, Wrt, DQ);

    // ---- embed (split) ----
    embed_kernel<<<(MROWS * 128 + 255) / 256, 256>>>(x_t, table, Xh, Xl);

    // ---- layers ----
    bf16 *curh = Xh, *curl = Xl, *nxth = Yh, *nxtl = Yl;
    for (int layer = 0; layer < DEPTHQ; layer++) {
        {
            // A (hidden state) has valid K only in 0..255 -> 8 chunks suffice
            dim3 grid((NEXT + LTN - 1) / LTN, MROWS / LTM);   // 3 x 64
            hgemm_split<<<grid, 128, SPLIT_SMEM>>>(
                curh, curl,
                Wieh + (size_t)layer * NEXT * KPAD, Wiel + (size_t)layer * NEXT * KPAD,
                NEXT, bie + layer * NEXT, NEXT, 1, 8,
                Ch, Cl, statep, gatep);
        }
        scan_kernel<<<BQ * SQ, SCAN_T>>>(gatep, statep, Ch, Cl,
                                         ostates + layer * BQ * SQ);
        {
            // combined has valid K 0..263 -> 9 chunks required
            dim3 grid(DQ / LTN, MROWS / LTM);                 // 2 x 64
            hgemm_split<<<grid, 128, SPLIT_SMEM>>>(
                Ch, Cl,
                Woth + (size_t)layer * DQ * KPAD, Wotl + (size_t)layer * DQ * KPAD,
                DQ, bo + layer * DQ, DQ, 0, 9,
                nxth, nxtl, nullptr, nullptr);
        }
        bf16* t;
        t = curh; curh = nxth; nxth = t;
        t = curl; curl = nxtl; nxtl = t;
    }

    // ---- layernorm -> fp16 ----
    layernorm_kernel<<<(MROWS * 32 + 255) / 256, 256>>>(curh, curl, gamma, beta, Af);

    // ---- logits + recon in ONE launch (fp16 HMMA, r12 config) ----
    {
        dim3 grid((VOCABQ + DQ) / TCN, MROWS / TCM);   // 252 x 32
        hgemm_f16<<<grid, 256, F16_SMEM>>>(Af, Bt, Wrt, bc, br, logits, recon);
    }
}

// round 16
// speedup vs baseline: 1.4878x; 1.4878x over previous
#include <cuda_runtime.h>
#include <cuda_fp16.h>
#include <cuda_bf16.h>
#include <math.h>
#include <stdint.h>

// ---------------- problem constants ----------------
#define BQ 2
#define LQ 2048
#define MROWS (BQ * LQ)     // 4096
#define DQ 256
#define SQ 8
#define DEPTHQ 4
#define DSQ (DQ + SQ)       // 264
#define NEXT 272            // 264 + 8 gate cols
#define KPAD 288            // padded K for layer GEMMs
#define VOCABQ 32000

typedef __nv_bfloat16 bf16;
typedef __nv_bfloat162 bf162;

// ---------------- scratch (no allocations; zero-init pads load-bearing) ----
__device__ __align__(256) bf16 g_Xh[MROWS * KPAD];
__device__ __align__(256) bf16 g_Xl[MROWS * KPAD];
__device__ __align__(256) bf16 g_Yh[MROWS * KPAD];
__device__ __align__(256) bf16 g_Yl[MROWS * KPAD];
__device__ __align__(256) bf16 g_Ch[MROWS * KPAD];
__device__ __align__(256) bf16 g_Cl[MROWS * KPAD];
__device__ float g_state[MROWS * SQ];
__device__ float g_gatebuf[MROWS * SQ];
__device__ __align__(256) bf16 g_Wieh[DEPTHQ * NEXT * KPAD];
__device__ __align__(256) bf16 g_Wiel[DEPTHQ * NEXT * KPAD];
__device__ __align__(256) bf16 g_Woth[DEPTHQ * DQ * KPAD];
__device__ __align__(256) bf16 g_Wotl[DEPTHQ * DQ * KPAD];
__device__ float g_bie[DEPTHQ * NEXT];
__device__ __align__(256) __half g_Af[MROWS * DQ];
__device__ __align__(256) __half g_Bt[(size_t)VOCABQ * DQ];
__device__ __align__(256) __half g_Wrt[DQ * DQ];

// ================= PTX helpers (base sm_103 ISA only) =================
__device__ __forceinline__ uint32_t smem_u32(const void* p) {
    uint32_t a;
    asm("{ .reg .u64 t; cvta.to.shared.u64 t, %1; cvt.u32.u64 %0, t; }" : "=r"(a) : "l"(p));
    return a;
}
__device__ __forceinline__ void cpa16(uint32_t dst, const void* src) {
    asm volatile("cp.async.cg.shared.global [%0], [%1], 16;" :: "r"(dst), "l"(src));
}
__device__ __forceinline__ void cpa_commit() { asm volatile("cp.async.commit_group;" ::: "memory"); }
__device__ __forceinline__ void cpa_wait2()  { asm volatile("cp.async.wait_group 2;" ::: "memory"); }
__device__ __forceinline__ void cpa_wait1()  { asm volatile("cp.async.wait_group 1;" ::: "memory"); }
__device__ __forceinline__ void cpa_wait0()  { asm volatile("cp.async.wait_group 0;" ::: "memory"); }

__device__ __forceinline__ void ldmx4(uint32_t* r, uint32_t addr) {
    asm volatile("ldmatrix.sync.aligned.m8n8.x4.shared.b16 {%0,%1,%2,%3}, [%4];"
                 : "=r"(r[0]), "=r"(r[1]), "=r"(r[2]), "=r"(r[3]) : "r"(addr));
}
__device__ __forceinline__ void mma16816(float* d, const uint32_t* a, uint32_t b0, uint32_t b1) {
    asm volatile(
        "mma.sync.aligned.m16n8k16.row.col.f32.f16.f16.f32 "
        "{%0,%1,%2,%3}, {%4,%5,%6,%7}, {%8,%9}, {%0,%1,%2,%3};"
        : "+f"(d[0]), "+f"(d[1]), "+f"(d[2]), "+f"(d[3])
        : "r"(a[0]), "r"(a[1]), "r"(a[2]), "r"(a[3]), "r"(b0), "r"(b1));
}
__device__ __forceinline__ void mma16816bf(float* d, const uint32_t* a, uint32_t b0, uint32_t b1) {
    asm volatile(
        "mma.sync.aligned.m16n8k16.row.col.f32.bf16.bf16.f32 "
        "{%0,%1,%2,%3}, {%4,%5,%6,%7}, {%8,%9}, {%0,%1,%2,%3};"
        : "+f"(d[0]), "+f"(d[1]), "+f"(d[2]), "+f"(d[3])
        : "r"(a[0]), "r"(a[1]), "r"(a[2]), "r"(a[3]), "r"(b0), "r"(b1));
}
__device__ __forceinline__ void splitbf(float v, bf16& h, bf16& l) {
    h = __float2bfloat16_rn(v);
    l = __float2bfloat16_rn(v - __bfloat162float(h));
}

// ================= fp16 GEMM (r12 proven): CTA 128x128, 8 warps (2x4), ====
// warp 64x32, depth-3 cp.async pipeline (4 buffers), logits+recon merged.
// Column tiles 0..249 -> logits (Bt, bc); tile 250..251 -> recon (Wrt, br).
#define TCM 128
#define TCN 128
#define F16_STG (TCM * 40 + TCN * 40)      // halfs per stage (10240 = 20480 B)
#define F16_NST 4
#define F16_SMEM (F16_NST * F16_STG * 2)   // 81920 B

__global__ __launch_bounds__(256, 2)
void hgemm_f16(const __half* __restrict__ A, const __half* __restrict__ Bt,
               const __half* __restrict__ Wrt,
               const float* __restrict__ bc, const float* __restrict__ br,
               float* __restrict__ logits, float* __restrict__ recon) {
    extern __shared__ __half hsm[];
    const uint32_t sb0 = smem_u32(hsm);
    const int tid = threadIdx.x;
    const int wid = tid >> 5, lane = tid & 31;
    const int wm = wid & 1, wn = wid >> 1;
    const int m0 = blockIdx.y * TCM;
    const int n0 = blockIdx.x * TCN;

    const bool is_recon = (n0 >= VOCABQ);
    const int cb = is_recon ? (n0 - VOCABQ) : n0;
    const __half* Bbase = is_recon ? (Wrt + (size_t)cb * DQ) : (Bt + (size_t)n0 * DQ);
    const float* bias = (is_recon ? br : bc) + cb;
    float* C = is_recon ? recon : logits;
    const int ldc = is_recon ? DQ : VOCABQ;

    float acc[4][4][4];
#pragma unroll
    for (int i = 0; i < 4; i++)
#pragma unroll
        for (int j = 0; j < 4; j++)
#pragma unroll
            for (int q = 0; q < 4; q++) acc[i][j][q] = 0.f;

    auto load_stage = [&](int s, int k0) {
        const uint32_t ab = sb0 + s * F16_STG * 2;
        const uint32_t bb = ab + TCM * 40 * 2;
#pragma unroll
        for (int it = 0; it < 2; it++) {
            int i = tid + it * 256;
            int r = i >> 2, c = i & 3;
            cpa16(ab + r * 80 + c * 16, A + (size_t)(m0 + r) * DQ + k0 + c * 8);
        }
#pragma unroll
        for (int it = 0; it < 2; it++) {
            int i = tid + it * 256;
            int r = i >> 2, c = i & 3;
            cpa16(bb + r * 80 + c * 16, Bbase + (size_t)r * DQ + k0 + c * 8);
        }
        cpa_commit();
    };

    load_stage(0, 0);
    load_stage(1, 32);
    load_stage(2, 64);
    const int lrow = lane & 15;
    const int lhalf = lane >> 4;

    for (int kt = 0; kt < 8; kt++) {
        if (kt <= 5)      cpa_wait2();
        else if (kt == 6) cpa_wait1();
        else              cpa_wait0();
        __syncthreads();
        if (kt < 5) load_stage((kt + 3) % F16_NST, (kt + 3) * 32);

        const uint32_t ab = sb0 + (kt % F16_NST) * F16_STG * 2;
        const uint32_t bb = ab + TCM * 40 * 2;
#pragma unroll
        for (int ks = 0; ks < 2; ks++) {
            const int chunk = ks * 2 + lhalf;
            uint32_t af[4][4], bf[2][4];
#pragma unroll
            for (int mi = 0; mi < 4; mi++)
                ldmx4(af[mi], ab + (wm * 64 + mi * 16 + lrow) * 80 + chunk * 16);
#pragma unroll
            for (int bj = 0; bj < 2; bj++)
                ldmx4(bf[bj], bb + (wn * 32 + bj * 16 + lrow) * 80 + chunk * 16);
#pragma unroll
            for (int mi = 0; mi < 4; mi++)
#pragma unroll
                for (int nj = 0; nj < 4; nj++) {
                    int bj = nj >> 1, hi = nj & 1;
                    mma16816(acc[mi][nj], af[mi], bf[bj][hi], bf[bj][hi + 2]);
                }
        }
    }

    const int g = lane >> 2, tig = lane & 3;
#pragma unroll
    for (int mi = 0; mi < 4; mi++) {
#pragma unroll
        for (int nj = 0; nj < 4; nj++) {
            int col = wn * 32 + nj * 8 + 2 * tig;         // local within tile
            float bx = __ldg(bias + col), by = __ldg(bias + col + 1);
            int row0 = m0 + wm * 64 + mi * 16 + g;
            size_t o0 = (size_t)row0 * ldc + cb + col;
            *(float2*)(C + o0) =
                make_float2(acc[mi][nj][0] + bx, acc[mi][nj][1] + by);
            *(float2*)(C + o0 + (size_t)8 * ldc) =
                make_float2(acc[mi][nj][2] + bx, acc[mi][nj][3] + by);
        }
    }
}

// ================= bf16-split GEMM, single-sync depth-2+ (3 buffers) ======
// C = (Ah+Al)[M][K] * (Bh+Bl)[N][K]^T + bias  (3-term compensated)
// CTA 64x128, 4 warps, warp 64x32, K = NKT*32 (compile-time chunk count).
#define LTM 64
#define LTN 128
#define SAH 0
#define SAL (64 * 40)
#define SBH (2 * 64 * 40)
#define SBL (2 * 64 * 40 + 128 * 40)
#define STG (2 * 64 * 40 + 2 * 128 * 40)   // bf16 elems per stage (15360)
#define SPLIT_NST 3
#define SPLIT_SMEM (SPLIT_NST * STG * 2)   // bytes = 92160

template <int NKT, int MODE>
__global__ __launch_bounds__(128)
void hgemm_split(const bf16* __restrict__ Ah, const bf16* __restrict__ Al,
                 const bf16* __restrict__ Bh, const bf16* __restrict__ Bl,
                 int nrowsB, const float* __restrict__ bias, int nbias,
                 bf16* __restrict__ outh, bf16* __restrict__ outl,
                 float* __restrict__ statep, float* __restrict__ gatep) {
    extern __shared__ bf16 sm[];
    const int tid = threadIdx.x;
    const int wn = tid >> 5, lane = tid & 31;
    const int m0 = blockIdx.y * LTM;
    const int n0 = blockIdx.x * LTN;

    float acc[4][4][4];
#pragma unroll
    for (int i = 0; i < 4; i++)
#pragma unroll
        for (int j = 0; j < 4; j++)
#pragma unroll
            for (int q = 0; q < 4; q++) acc[i][j][q] = 0.f;

    const uint32_t sb0 = smem_u32(sm);

    auto load_stage = [&](int s, int k0) {
        const uint32_t sb = sb0 + s * STG * 2;
#pragma unroll
        for (int it = 0; it < 2; it++) {
            int i = tid + it * 128;                 // A rows 64 x 4 chunks
            int r = i >> 2, c = i & 3;
            size_t goff = (size_t)(m0 + r) * KPAD + k0 + c * 8;
            cpa16(sb + (SAH + r * 40) * 2 + c * 16, Ah + goff);
            cpa16(sb + (SAL + r * 40) * 2 + c * 16, Al + goff);
        }
#pragma unroll
        for (int it = 0; it < 4; it++) {
            int i = tid + it * 128;                 // B rows 128 x 4 chunks
            int r = i >> 2, c = i & 3;
            int rr = n0 + r; if (rr >= nrowsB) rr = 0;
            size_t goff = (size_t)rr * KPAD + k0 + c * 8;
            cpa16(sb + (SBH + r * 40) * 2 + c * 16, Bh + goff);
            cpa16(sb + (SBL + r * 40) * 2 + c * 16, Bl + goff);
        }
        cpa_commit();
    };

    load_stage(0, 0);
    load_stage(1, 32);
    const int lrow = lane & 15;
    const int lhalf = lane >> 4;

    for (int kt = 0; kt < NKT; kt++) {
        if (kt < NKT - 1) cpa_wait1(); else cpa_wait0();
        __syncthreads();                             // fences compute kt-1
        if (kt + 2 < NKT) load_stage((kt + 2) % SPLIT_NST, (kt + 2) * 32);

        const uint32_t sb = sb0 + (kt % SPLIT_NST) * STG * 2;
#pragma unroll
        for (int ks = 0; ks < 2; ks++) {
            const int chunk = ks * 2 + lhalf;
            uint32_t afh[4][4], afl[4][4], bfh[2][4], bfl[2][4];
#pragma unroll
            for (int mi = 0; mi < 4; mi++) {
                int r = mi * 16 + lrow;
                ldmx4(afh[mi], sb + (SAH + r * 40) * 2 + chunk * 16);
                ldmx4(afl[mi], sb + (SAL + r * 40) * 2 + chunk * 16);
            }
#pragma unroll
            for (int bj = 0; bj < 2; bj++) {
                int r = wn * 32 + bj * 16 + lrow;
                ldmx4(bfh[bj], sb + (SBH + r * 40) * 2 + chunk * 16);
                ldmx4(bfl[bj], sb + (SBL + r * 40) * 2 + chunk * 16);
            }
#pragma unroll
            for (int mi = 0; mi < 4; mi++)
#pragma unroll
                for (int nj = 0; nj < 4; nj++) {
                    int bj = nj >> 1, hi = nj & 1;
                    mma16816bf(acc[mi][nj], afh[mi], bfh[bj][hi], bfh[bj][hi + 2]);
                    mma16816bf(acc[mi][nj], afl[mi], bfh[bj][hi], bfh[bj][hi + 2]);
                    mma16816bf(acc[mi][nj], afh[mi], bfl[bj][hi], bfl[bj][hi + 2]);
                }
        }
    }

    const int g = lane >> 2, tig = lane & 3;
#pragma unroll
    for (int mi = 0; mi < 4; mi++) {
#pragma unroll
        for (int nj = 0; nj < 4; nj++) {
            int col = n0 + wn * 32 + nj * 8 + 2 * tig;
            if (col >= nbias) continue;
            float bx = __ldg(bias + col), by = __ldg(bias + col + 1);
            int r0 = m0 + mi * 16 + g;
#pragma unroll
            for (int half = 0; half < 2; half++) {
                int r = r0 + half * 8;
                float v0 = acc[mi][nj][half * 2 + 0] + bx;
                float v1 = acc[mi][nj][half * 2 + 1] + by;
                if (MODE == 0 || col < 256) {
                    bf16 h0, l0, h1, l1;
                    splitbf(v0, h0, l0); splitbf(v1, h1, l1);
                    *(bf162*)(outh + (size_t)r * KPAD + col) = __halves2bfloat162(h0, h1);
                    *(bf162*)(outl + (size_t)r * KPAD + col) = __halves2bfloat162(l0, l1);
                } else if (col < 264) {
                    *(float2*)(statep + r * SQ + (col - 256)) = make_float2(v0, v1);
                } else {  // 264..271
                    gatep[r * SQ + (col - 264)]     = 1.f / (1.f + expf(-v0));
                    gatep[r * SQ + (col - 264) + 1] = 1.f / (1.f + expf(-v1));
                }
            }
        }
    }
}

// ================= weight prep kernels =================
__global__ void prep_wie(const float* __restrict__ Wi, const float* __restrict__ Wg,
                         const float* __restrict__ bi, const float* __restrict__ bg,
                         bf16* __restrict__ Wh, bf16* __restrict__ Wl,
                         float* __restrict__ bie) {
    int n = blockIdx.x, l = blockIdx.y, k = threadIdx.x;   // k in 0..255
    const float* Wil = Wi + (size_t)l * DQ * DSQ;
    const float* Wgl = Wg + (size_t)l * DSQ * SQ;
    float w;
    if (n < DSQ) {
        w = Wil[k * DSQ + n];
    } else {
        int s = n - DSQ;
        float a = 0.f;
        for (int e = 0; e < DSQ; e++) a += Wil[k * DSQ + e] * Wgl[e * SQ + s];
        w = a;
    }
    bf16 h, lo; splitbf(w, h, lo);
    size_t o = ((size_t)l * NEXT + n) * KPAD + k;
    Wh[o] = h; Wl[o] = lo;
    if (k == 0) {
        float b;
        if (n < DSQ) b = bi[l * DSQ + n];
        else {
            int s = n - DSQ;
            float a = bg[l * SQ + s];
            for (int e = 0; e < DSQ; e++) a += bi[l * DSQ + e] * Wgl[e * SQ + s];
            b = a;
        }
        bie[l * NEXT + n] = b;
    }
}

__global__ void prep_wot(const float* __restrict__ Wo,
                         bf16* __restrict__ Wh, bf16* __restrict__ Wl) {
    int e = blockIdx.x, l = blockIdx.y, d = threadIdx.x;
    float w = Wo[((size_t)l * DSQ + e) * DQ + d];
    bf16 h, lo; splitbf(w, h, lo);
    size_t o = ((size_t)l * DQ + d) * KPAD + e;
    Wh[o] = h; Wl[o] = lo;
}

// generic [256][ncols] f32 -> [ncols][256] fp16 transpose
__global__ __launch_bounds__(256)
void transpose_f32_to_f16(const float* __restrict__ src, __half* __restrict__ dst, int ncols) {
    __shared__ float t[32][33];
    const int n0 = blockIdx.x * 32;
    const int k0 = blockIdx.y * 32;
    const int tx = threadIdx.x, ty = threadIdx.y;   // 32 x 8
#pragma unroll
    for (int r = 0; r < 4; r++)
        t[ty * 4 + r][tx] = src[(size_t)(k0 + ty * 4 + r) * ncols + n0 + tx];
    __syncthreads();
#pragma unroll
    for (int r = 0; r < 4; r++)
        dst[(size_t)(n0 + ty * 4 + r) * DQ + k0 + tx] = __float2half_rn(t[tx][ty * 4 + r]);
}

// ---------------- embed gather -> split bf16 ----------------
__global__ void embed_kernel(const int* __restrict__ x_t,
                             const float* __restrict__ table,
                             bf16* __restrict__ hh, bf16* __restrict__ hl) {
    int i = blockIdx.x * blockDim.x + threadIdx.x;   // over MROWS*128
    if (i >= MROWS * 128) return;
    int row = i >> 7;
    int d0 = (i & 127) * 2;
    const float* tr = table + (size_t)x_t[row] * DQ + d0;
    float v0 = tr[0], v1 = tr[1];
    bf16 h0, l0, h1, l1;
    splitbf(v0, h0, l0); splitbf(v1, h1, l1);
    *(bf162*)(hh + (size_t)row * KPAD + d0) = __halves2bfloat162(h0, h1);
    *(bf162*)(hl + (size_t)row * KPAD + d0) = __halves2bfloat162(l0, l1);
}

// ---------------- parallel scan over L ----------------
#define SCAN_T 256
#define SCAN_STEPS (LQ / SCAN_T)   // 8

__global__ __launch_bounds__(SCAN_T)
void scan_kernel(const float* __restrict__ gate,
                 const float* __restrict__ state_in,
                 bf16* __restrict__ combh, bf16* __restrict__ combl,
                 float* __restrict__ out_states) {
    const int b = blockIdx.x >> 3;
    const int s = blockIdx.x & 7;
    const int t = threadIdx.x;
    const int l0 = t * SCAN_STEPS;

    float g[SCAN_STEPS], si[SCAN_STEPS];
#pragma unroll
    for (int u = 0; u < SCAN_STEPS; u++) {
        int idx = b * LQ + l0 + u;
        g[u]  = gate[idx * SQ + s];
        si[u] = state_in[idx * SQ + s];
    }

    float a = 1.f, bb = 0.f;
#pragma unroll
    for (int u = 0; u < SCAN_STEPS; u++) {
        a  = g[u] * a;
        bb = g[u] * bb + (1.f - g[u]) * si[u];
    }

    __shared__ float sa[SCAN_T], sbv[SCAN_T];
    sa[t] = a; sbv[t] = bb;
    __syncthreads();

#pragma unroll
    for (int off = 1; off < SCAN_T; off <<= 1) {
        float pa = 1.f, pb = 0.f, ca = sa[t], cb = sbv[t];
        if (t >= off) { pa = sa[t - off]; pb = sbv[t - off]; }
        __syncthreads();
        if (t >= off) { sa[t] = ca * pa; sbv[t] = ca * pb + cb; }
        __syncthreads();
    }

    float st = (t == 0) ? 0.f : sbv[t - 1];
#pragma unroll
    for (int u = 0; u < SCAN_STEPS; u++) {
        int idx = b * LQ + l0 + u;
        st = g[u] * st + (1.f - g[u]) * si[u];
        bf16 h, lo; splitbf(st, h, lo);
        combh[(size_t)idx * KPAD + DQ + s] = h;
        combl[(size_t)idx * KPAD + DQ + s] = lo;
    }
    if (t == SCAN_T - 1) out_states[b * SQ + s] = st;
}

// ---------------- layernorm: (hi+lo) fp32 math -> fp16 out ----------------
__global__ __launch_bounds__(256)
void layernorm_kernel(const bf16* __restrict__ xh, const bf16* __restrict__ xl,
                      const float* __restrict__ gamma, const float* __restrict__ beta,
                      __half* __restrict__ y) {
    int warp = (blockIdx.x * blockDim.x + threadIdx.x) >> 5;
    int lane = threadIdx.x & 31;
    if (warp >= MROWS) return;
    const bf16* xhr = xh + (size_t)warp * KPAD;
    const bf16* xlr = xl + (size_t)warp * KPAD;
    float v[8];
    float sum = 0.f;
#pragma unroll
    for (int i = 0; i < 8; i++) {
        int d = lane + i * 32;
        v[i] = __bfloat162float(xhr[d]) + __bfloat162float(xlr[d]);
        sum += v[i];
    }
#pragma unroll
    for (int o = 16; o; o >>= 1) sum += __shfl_xor_sync(0xFFFFFFFFu, sum, o);
    float mu = sum * (1.f / 256.f);
    float vs = 0.f;
#pragma unroll
    for (int i = 0; i < 8; i++) { float d = v[i] - mu; vs += d * d; }
#pragma unroll
    for (int o = 16; o; o >>= 1) vs += __shfl_xor_sync(0xFFFFFFFFu, vs, o);
    float r = rsqrtf(vs * (1.f / 256.f) + 1e-5f);
    __half* yr = y + (size_t)warp * DQ;
#pragma unroll
    for (int i = 0; i < 8; i++) {
        int d = lane + i * 32;
        yr[d] = __float2half_rn((v[i] - mu) * r * gamma[d] + beta[d]);
    }
}

// ---------------- launch ----------------
extern "C" void kernel_launch(void* const* d_in, const int* in_sizes, int n_in,
                              void* d_out, int out_size) {
    const int*   x_t   = (const int*)  d_in[0];
    const float* table = (const float*)d_in[1];
    const float* Wi    = (const float*)d_in[2];
    const float* bi    = (const float*)d_in[3];
    const float* Wg    = (const float*)d_in[4];
    const float* bg    = (const float*)d_in[5];
    const float* Wo    = (const float*)d_in[6];
    const float* bo    = (const float*)d_in[7];
    const float* gamma = (const float*)d_in[8];
    const float* beta  = (const float*)d_in[9];
    const float* Wc    = (const float*)d_in[10];
    const float* bc    = (const float*)d_in[11];
    const float* Wr    = (const float*)d_in[12];
    const float* br    = (const float*)d_in[13];

    float* out = (float*)d_out;
    const size_t logits_elems = (size_t)MROWS * VOCABQ;
    const size_t recon_elems  = (size_t)MROWS * DQ;
    float* logits  = out;
    float* recon   = out + logits_elems;
    float* ostates = out + logits_elems + recon_elems;

    bf16 *Xh, *Xl, *Yh, *Yl, *Ch, *Cl, *Wieh, *Wiel, *Woth, *Wotl;
    __half *Af, *Bt, *Wrt;
    float *statep, *gatep, *bie;
    cudaGetSymbolAddress((void**)&Xh, g_Xh);     cudaGetSymbolAddress((void**)&Xl, g_Xl);
    cudaGetSymbolAddress((void**)&Yh, g_Yh);     cudaGetSymbolAddress((void**)&Yl, g_Yl);
    cudaGetSymbolAddress((void**)&Ch, g_Ch);     cudaGetSymbolAddress((void**)&Cl, g_Cl);
    cudaGetSymbolAddress((void**)&Wieh, g_Wieh); cudaGetSymbolAddress((void**)&Wiel, g_Wiel);
    cudaGetSymbolAddress((void**)&Woth, g_Woth); cudaGetSymbolAddress((void**)&Wotl, g_Wotl);
    cudaGetSymbolAddress((void**)&Af, g_Af);     cudaGetSymbolAddress((void**)&Bt, g_Bt);
    cudaGetSymbolAddress((void**)&Wrt, g_Wrt);
    cudaGetSymbolAddress((void**)&statep, g_state);
    cudaGetSymbolAddress((void**)&gatep, g_gatebuf);
    cudaGetSymbolAddress((void**)&bie, g_bie);

    cudaFuncSetAttribute(hgemm_split<8, 1>, cudaFuncAttributeMaxDynamicSharedMemorySize, SPLIT_SMEM);
    cudaFuncSetAttribute(hgemm_split<9, 0>, cudaFuncAttributeMaxDynamicSharedMemorySize, SPLIT_SMEM);
    cudaFuncSetAttribute(hgemm_f16,   cudaFuncAttributeMaxDynamicSharedMemorySize, F16_SMEM);

    // ---- weight prep ----
    prep_wie<<<dim3(NEXT, DEPTHQ), 256>>>(Wi, Wg, bi, bg, Wieh, Wiel, bie);
    prep_wot<<<dim3(DSQ, DEPTHQ), 256>>>(Wo, Woth, Wotl);
    transpose_f32_to_f16<<<dim3(VOCABQ / 32, DQ / 32), dim3(32, 8)>>>(Wc, Bt, VOCABQ);
    transpose_f32_to_f16<<<dim3(DQ / 32, DQ / 32), dim3(32, 8)>>>(Wr, Wrt, DQ);

    // ---- embed (split) ----
    embed_kernel<<<(MROWS * 128 + 255) / 256, 256>>>(x_t, table, Xh, Xl);

    // ---- layers ----
    bf16 *curh = Xh, *curl = Xl, *nxth = Yh, *nxtl = Yl;
    for (int layer = 0; layer < DEPTHQ; layer++) {
        {
            // A (hidden state) valid K only 0..255 -> 8 chunks (compile-time)
            dim3 grid((NEXT + LTN - 1) / LTN, MROWS / LTM);   // 3 x 64
            hgemm_split<8, 1><<<grid, 128, SPLIT_SMEM>>>(
                curh, curl,
                Wieh + (size_t)layer * NEXT * KPAD, Wiel + (size_t)layer * NEXT * KPAD,
                NEXT, bie + layer * NEXT, NEXT,
                Ch, Cl, statep, gatep);
        }
        scan_kernel<<<BQ * SQ, SCAN_T>>>(gatep, statep, Ch, Cl,
                                         ostates + layer * BQ * SQ);
        {
            // combined valid K 0..263 -> 9 chunks (compile-time)
            dim3 grid(DQ / LTN, MROWS / LTM);                 // 2 x 64
            hgemm_split<9, 0><<<grid, 128, SPLIT_SMEM>>>(
                Ch, Cl,
                Woth + (size_t)layer * DQ * KPAD, Wotl + (size_t)layer * DQ * KPAD,
                DQ, bo + layer * DQ, DQ,
                nxth, nxtl, nullptr, nullptr);
        }
        bf16* t;
        t = curh; curh = nxth; nxth = t;
        t = curl; curl = nxtl; nxtl = t;
    }

    // ---- layernorm -> fp16 ----
    layernorm_kernel<<<(MROWS * 32 + 255) / 256, 256>>>(curh, curl, gamma, beta, Af);

    // ---- logits + recon in ONE launch (fp16 HMMA, r12 config) ----
    {
        dim3 grid((VOCABQ + DQ) / TCN, MROWS / TCM);   // 252 x 32
        hgemm_f16<<<grid, 256, F16_SMEM>>>(Af, Bt, Wrt, bc, br, logits, recon);
    }
}